// round 3
// baseline (speedup 1.0000x reference)
#include <cuda_runtime.h>
#include <math.h>
#include <stdint.h>

#define BATCH   16
#define NHEADS  32
#define G       8      // kv heads
#define RQ      4      // query heads per kv head
#define D       128
#define BLK     256    // cache block == kv chunk per CTA
#define MAXB    16     // blocks per sequence
#define TS      64     // positions per tile
#define PSTR4   (G * (D / 4))   // float4 stride between positions = 256
#define NEG_INF (-1e30f)
#define QK_SCALE 0.08838834764831845f  // 1/sqrt(128)

// split-KV partial results: [B, G, chunk, rq]
__device__ float g_pm  [BATCH * G * MAXB * RQ];
__device__ float g_pl  [BATCH * G * MAXB * RQ];
__device__ float g_pacc[BATCH * G * MAXB * RQ * D];

__device__ __forceinline__ void cp16(uint32_t dst, const void* src) {
    asm volatile("cp.async.cg.shared.global [%0], [%1], 16;" :: "r"(dst), "l"(src));
}
__device__ __forceinline__ void cp_commit() {
    asm volatile("cp.async.commit_group;");
}
template <int N>
__device__ __forceinline__ void cp_wait() {
    asm volatile("cp.async.wait_group %0;" :: "n"(N));
}

// smem layout (float4 units):
//   [0,    2048)  K buf 0   (64 rows x 32 chunks, row-XOR swizzled)
//   [2048, 4096)  K buf 1
//   [4096, 4224)  q         [chunk][head] float4, pre-scaled
//   [4224, 4288)  p tile    [pos] float4 (4 heads' exp weights)
//   [4288, 4296)  reduction scratch (32 floats)
#define RED_WMAX 0
#define RED_WSUM 8
#define RED_MNEW 16
#define RED_AL   20
#define RED_MRUN 24
#define RED_LRUN 28
#define SMEM_F4  4296
#define SMEM_BYTES (SMEM_F4 * 16)   // 68736 B -> 3 CTAs/SM

__global__ __launch_bounds__(128, 3)
void attn_chunk_kernel(const float* __restrict__ q,
                       const float* __restrict__ knew,
                       const float* __restrict__ vnew,
                       const float* __restrict__ kcache,
                       const float* __restrict__ vcache,
                       const int*   __restrict__ ctx_lens,
                       const int*   __restrict__ btab,
                       const int*   __restrict__ slot_map)
{
    const int c = blockIdx.x;   // chunk
    const int g = blockIdx.y;   // kv head
    const int b = blockIdx.z;   // sequence

    const int ctx   = ctx_lens[b];
    const int start = c * BLK;
    if (start >= ctx) return;
    const int npos = min(BLK, ctx - start);

    extern __shared__ float4 sm4[];
    float4* kb[2] = { sm4, sm4 + 2048 };
    float4* qsm  = sm4 + 4096;
    float4* pt   = sm4 + 4224;
    float*  red  = (float*)(sm4 + 4288);

    const int tid  = threadIdx.x;
    const int lane = tid & 31;
    const int warp = tid >> 5;

    const int blkid = btab[b * MAXB + c];
    const float4* kbase = (const float4*)kcache + (size_t)blkid * BLK * PSTR4 + g * (D / 4);
    const float4* vbase = (const float4*)vcache + (size_t)blkid * BLK * PSTR4 + g * (D / 4);

    const int lastLocal = (slot_map[b] >= 0) ? (ctx - 1 - start) : -1000000;
    const float4* knp = (const float4*)knew + (size_t)(b * G + g) * (D / 4);
    const float4* vnp = (const float4*)vnew + (size_t)(b * G + g) * (D / 4);

    const uint32_t kb_addr[2] = { (uint32_t)__cvta_generic_to_shared(kb[0]),
                                  (uint32_t)__cvta_generic_to_shared(kb[1]) };

    const int ntiles = (npos + TS - 1) / TS;

    // prologue: K tile 0 -> buf 0 (group 0)
    {
        int rows = min(TS, npos);
        #pragma unroll
        for (int j = 0; j < 16; ++j) {
            int idx = tid + 128 * j;
            int row = idx >> 5, cc = idx & 31;
            if (row < rows)
                cp16(kb_addr[0] + (uint32_t)((row * 32 + (cc ^ (row & 31))) * 16),
                     kbase + (size_t)row * PSTR4 + cc);
        }
        cp_commit();
    }

    // q into smem, pre-scaled, layout [chunk][head]
    {
        const float4* qb = (const float4*)q + (size_t)(b * NHEADS + g * RQ) * (D / 4);
        int cc = tid >> 2, h = tid & 3;
        float4 t4 = qb[h * 32 + cc];
        t4.x *= QK_SCALE; t4.y *= QK_SCALE; t4.z *= QK_SCALE; t4.w *= QK_SCALE;
        qsm[cc * 4 + h] = t4;
    }
    if (tid < 4) { red[RED_MRUN + tid] = NEG_INF; red[RED_LRUN + tid] = 0.f; }

    float4 acc0 = make_float4(0.f, 0.f, 0.f, 0.f);
    float4 acc1 = acc0, acc2 = acc0, acc3 = acc0;

    const int spos = tid & 63;          // position within tile (score phase)
    const int h0   = (tid >> 6) * 2;    // head pair

    for (int t = 0; t < ntiles; ++t) {
        const int t0 = t * TS;

        // prefetch K(t+1) (writes buffer last read in tile t-1; safe: all warps
        // passed the post-score barrier of t-1 before any warp reaches here)
        if (t + 1 < ntiles) {
            int t1 = t0 + TS;
            int rows = min(TS, npos - t1);
            uint32_t dst = kb_addr[(t + 1) & 1];
            #pragma unroll
            for (int j = 0; j < 16; ++j) {
                int idx = tid + 128 * j;
                int row = idx >> 5, cc = idx & 31;
                if (row < rows)
                    cp16(dst + (uint32_t)((row * 32 + (cc ^ (row & 31))) * 16),
                         kbase + (size_t)(t1 + row) * PSTR4 + cc);
            }
        }
        cp_commit();                 // unconditional: keeps wait<1> == "K(t) done"

        cp_wait<1>();
        __syncthreads();             // (1) K(t) visible CTA-wide

        // fresh-token K substitution
        const int fr = lastLocal - t0;
        if (fr >= 0 && fr < TS) {
            if (tid < 32)
                kb[t & 1][fr * 32 + (tid ^ (fr & 31))] = knp[tid];
            __syncthreads();
        }

        // ---- score phase: thread = (position, head pair) ----
        float s0 = NEG_INF, s1 = NEG_INF;
        const bool pvalid = (t0 + spos) < npos;
        if (pvalid) {
            const float4* krow = kb[t & 1] + spos * 32;
            const int rsw = spos & 31;
            float a0 = 0.f, a1 = 0.f;
            #pragma unroll 8
            for (int cc = 0; cc < 32; ++cc) {
                float4 k4 = krow[cc ^ rsw];
                float4 qa = qsm[cc * 4 + h0];
                float4 qd = qsm[cc * 4 + h0 + 1];
                a0 += k4.x * qa.x + k4.y * qa.y + k4.z * qa.z + k4.w * qa.w;
                a1 += k4.x * qd.x + k4.y * qd.y + k4.z * qd.z + k4.w * qd.w;
            }
            s0 = a0; s1 = a1;
        }

        // warp max (2 heads per thread)
        float w0 = s0, w1 = s1;
        #pragma unroll
        for (int off = 16; off > 0; off >>= 1) {
            w0 = fmaxf(w0, __shfl_xor_sync(0xffffffffu, w0, off));
            w1 = fmaxf(w1, __shfl_xor_sync(0xffffffffu, w1, off));
        }
        if (lane == 0) { red[RED_WMAX + warp * 2] = w0; red[RED_WMAX + warp * 2 + 1] = w1; }
        __syncthreads();             // (2)

        if (tid < 4) {  // head h: its two warps are 2*(h>>1), 2*(h>>1)+1
            int h = tid;
            float mt = fmaxf(red[RED_WMAX + 4 * (h >> 1) + (h & 1)],
                             red[RED_WMAX + 4 * (h >> 1) + 2 + (h & 1)]);
            float mo = red[RED_MRUN + h];
            float mn = fmaxf(mo, mt);
            red[RED_MNEW + h] = mn;
            red[RED_AL + h]   = __expf(mo - mn);
            red[RED_MRUN + h] = mn;
        }
        __syncthreads();             // (3)

        float e0 = 0.f, e1 = 0.f;
        if (pvalid) {
            e0 = __expf(s0 - red[RED_MNEW + h0]);
            e1 = __expf(s1 - red[RED_MNEW + h0 + 1]);
        }
        *(float2*)((float*)pt + spos * 4 + h0) = make_float2(e0, e1);

        // warp sum of e
        float u0 = e0, u1 = e1;
        #pragma unroll
        for (int off = 16; off > 0; off >>= 1) {
            u0 += __shfl_xor_sync(0xffffffffu, u0, off);
            u1 += __shfl_xor_sync(0xffffffffu, u1, off);
        }
        if (lane == 0) { red[RED_WSUM + warp * 2] = u0; red[RED_WSUM + warp * 2 + 1] = u1; }
        __syncthreads();             // (4) pt + sums visible

        if (tid < 4) {
            int h = tid;
            float lt = red[RED_WSUM + 4 * (h >> 1) + (h & 1)] +
                       red[RED_WSUM + 4 * (h >> 1) + 2 + (h & 1)];
            red[RED_LRUN + h] = red[RED_LRUN + h] * red[RED_AL + h] + lt;
        }

        // ---- PV phase: V streamed straight from HBM, 4 rows in flight ----
        {
            const float al0 = red[RED_AL + 0], al1 = red[RED_AL + 1];
            const float al2 = red[RED_AL + 2], al3 = red[RED_AL + 3];
            acc0.x *= al0; acc0.y *= al0; acc0.z *= al0; acc0.w *= al0;
            acc1.x *= al1; acc1.y *= al1; acc1.z *= al1; acc1.w *= al1;
            acc2.x *= al2; acc2.y *= al2; acc2.z *= al2; acc2.w *= al2;
            acc3.x *= al3; acc3.y *= al3; acc3.z *= al3; acc3.w *= al3;

            const int pvn = min(TS, npos - t0);
            for (int p0 = warp; p0 < pvn; p0 += 16) {
                float4 v4[4], p4[4];
                #pragma unroll
                for (int j = 0; j < 4; ++j) {
                    const int p = p0 + 4 * j;
                    if (p < pvn) {
                        v4[j] = (t0 + p == lastLocal) ? vnp[lane]
                                : vbase[(size_t)(t0 + p) * PSTR4 + lane];
                        p4[j] = pt[p];
                    } else {
                        v4[j] = make_float4(0.f, 0.f, 0.f, 0.f);
                        p4[j] = make_float4(0.f, 0.f, 0.f, 0.f);
                    }
                }
                #pragma unroll
                for (int j = 0; j < 4; ++j) {
                    acc0.x += p4[j].x * v4[j].x; acc0.y += p4[j].x * v4[j].y;
                    acc0.z += p4[j].x * v4[j].z; acc0.w += p4[j].x * v4[j].w;
                    acc1.x += p4[j].y * v4[j].x; acc1.y += p4[j].y * v4[j].y;
                    acc1.z += p4[j].y * v4[j].z; acc1.w += p4[j].y * v4[j].w;
                    acc2.x += p4[j].z * v4[j].x; acc2.y += p4[j].z * v4[j].y;
                    acc2.z += p4[j].z * v4[j].z; acc2.w += p4[j].z * v4[j].w;
                    acc3.x += p4[j].w * v4[j].x; acc3.y += p4[j].w * v4[j].y;
                    acc3.z += p4[j].w * v4[j].z; acc3.w += p4[j].w * v4[j].w;
                }
            }
        }
    }

    // ---- epilogue: combine 4 warps' partial acc, write split-KV partials ----
    __syncthreads();
    float4* ab = sm4;   // reuse K buf 0: [warp][head][lane] float4 = 512 f4
    ab[(warp * 4 + 0) * 32 + lane] = acc0;
    ab[(warp * 4 + 1) * 32 + lane] = acc1;
    ab[(warp * 4 + 2) * 32 + lane] = acc2;
    ab[(warp * 4 + 3) * 32 + lane] = acc3;
    __syncthreads();

    const float* abf = (const float*)ab;
    const size_t pidx = ((size_t)(b * G + g) * MAXB + c) * RQ;
    #pragma unroll
    for (int e = tid; e < RQ * D; e += 128) {
        int h = e >> 7, d = e & 127;
        float A = abf[(0 * 4 + h) * 128 + d] + abf[(1 * 4 + h) * 128 + d]
                + abf[(2 * 4 + h) * 128 + d] + abf[(3 * 4 + h) * 128 + d];
        g_pacc[(pidx + h) * D + d] = A;
    }
    if (tid < 4) {
        g_pm[pidx + tid] = red[RED_MRUN + tid];
        g_pl[pidx + tid] = red[RED_LRUN + tid];
    }
}

__global__ __launch_bounds__(128)
void attn_combine_kernel(const int* __restrict__ ctx_lens,
                         float* __restrict__ out)
{
    const int h = blockIdx.x;   // 0..31
    const int b = blockIdx.y;   // 0..15
    const int g  = h >> 2;
    const int hh = h & 3;
    const int nc = (ctx_lens[b] + BLK - 1) / BLK;
    const int d  = threadIdx.x;

    const size_t base = ((size_t)(b * G + g) * MAXB) * RQ + hh;

    // all 48 loads issued together (independent, predicated) -> one DRAM round
    float mv[MAXB], lv[MAXB], av[MAXB];
    #pragma unroll
    for (int c = 0; c < MAXB; ++c) {
        if (c < nc) {
            mv[c] = g_pm[base + (size_t)c * RQ];
            lv[c] = g_pl[base + (size_t)c * RQ];
            av[c] = g_pacc[(base + (size_t)c * RQ) * D + d];
        } else { mv[c] = NEG_INF; lv[c] = 0.f; av[c] = 0.f; }
    }
    float M = mv[0];
    #pragma unroll
    for (int c = 1; c < MAXB; ++c) M = fmaxf(M, mv[c]);
    float L = 0.f, A = 0.f;
    #pragma unroll
    for (int c = 0; c < MAXB; ++c) {
        const float e = __expf(mv[c] - M);
        L += e * lv[c];
        A += e * av[c];
    }
    out[((size_t)b * NHEADS + h) * D + d] = A / L;
}

extern "C" void kernel_launch(void* const* d_in, const int* in_sizes, int n_in,
                              void* d_out, int out_size)
{
    const float* q    = (const float*)d_in[0];
    const float* k    = (const float*)d_in[1];
    const float* v    = (const float*)d_in[2];
    const float* kc   = (const float*)d_in[3];
    const float* vc   = (const float*)d_in[4];
    const int*   ctx  = (const int*)d_in[5];
    const int*   btab = (const int*)d_in[6];
    const int*   smap = (const int*)d_in[7];
    float* out = (float*)d_out;

    static int smem_set = 0;
    if (!smem_set) {
        cudaFuncSetAttribute(attn_chunk_kernel,
                             cudaFuncAttributeMaxDynamicSharedMemorySize, SMEM_BYTES);
        smem_set = 1;
    }

    dim3 grid(MAXB, G, BATCH);
    attn_chunk_kernel<<<grid, 128, SMEM_BYTES>>>(q, k, v, kc, vc, ctx, btab, smap);
    attn_combine_kernel<<<dim3(NHEADS, BATCH), D>>>(ctx, out);
}

// round 4
// speedup vs baseline: 1.2880x; 1.2880x over previous
#include <cuda_runtime.h>
#include <math.h>
#include <stdint.h>

#define BATCH   16
#define NHEADS  32
#define G       8      // kv heads
#define RQ      4      // query heads per kv head
#define D       128
#define BLK     256    // cache block == kv chunk per CTA
#define MAXB    16     // blocks per sequence
#define TS      32     // positions per tile
#define PSTR4   (G * (D / 4))   // float4 stride between positions = 256
#define NEG_INF (-1e30f)
#define QK_SCALE 0.08838834764831845f  // 1/sqrt(128)

// split-KV partial results: [B, G, chunk, rq]
__device__ float g_pm  [BATCH * G * MAXB * RQ];
__device__ float g_pl  [BATCH * G * MAXB * RQ];
__device__ float g_pacc[BATCH * G * MAXB * RQ * D];

__device__ __forceinline__ void cp16(uint32_t dst, const void* src) {
    asm volatile("cp.async.cg.shared.global [%0], [%1], 16;" :: "r"(dst), "l"(src));
}
__device__ __forceinline__ void cp_commit() {
    asm volatile("cp.async.commit_group;");
}
template <int N>
__device__ __forceinline__ void cp_wait() {
    asm volatile("cp.async.wait_group %0;" :: "n"(N));
}

// smem layout (float4 units):
//   [0,    1024)  K buf 0   (32 rows x 32 chunks, row-XOR swizzled)
//   [1024, 2048)  K buf 1
//   [2048, 3072)  V buf 0
//   [3072, 4096)  V buf 1
//   [4096, 4224)  q   [chunk][head] float4, pre-scaled
//   [4224, 4256)  pt  [pos] float4 = 4 heads' exp weights
//   [4256, 4258)  red scratch (al[4] + pad)
#define SMEM_F4  4258
#define SMEM_BYTES (SMEM_F4 * 16)   // 68128 B -> 3 CTAs/SM

__global__ __launch_bounds__(128, 3)
void attn_chunk_kernel(const float* __restrict__ q,
                       const float* __restrict__ knew,
                       const float* __restrict__ vnew,
                       const float* __restrict__ kcache,
                       const float* __restrict__ vcache,
                       const int*   __restrict__ ctx_lens,
                       const int*   __restrict__ btab,
                       const int*   __restrict__ slot_map)
{
    const int c = blockIdx.x;   // chunk
    const int g = blockIdx.y;   // kv head
    const int b = blockIdx.z;   // sequence

    const int ctx   = ctx_lens[b];
    const int start = c * BLK;
    if (start >= ctx) return;
    const int npos = min(BLK, ctx - start);

    extern __shared__ float4 sm4[];
    float4* kb[2] = { sm4,        sm4 + 1024 };
    float4* vb[2] = { sm4 + 2048, sm4 + 3072 };
    float4* qsm  = sm4 + 4096;
    float4* pt   = sm4 + 4224;
    float*  red  = (float*)(sm4 + 4256);   // al[0..3]

    const int tid  = threadIdx.x;
    const int lane = tid & 31;    // position within tile (score) / V lane (PV)
    const int warp = tid >> 5;    // head (score) / position group (PV)

    const int blkid = btab[b * MAXB + c];
    const float4* kbase = (const float4*)kcache + (size_t)blkid * BLK * PSTR4 + g * (D / 4);
    const float4* vbase = (const float4*)vcache + (size_t)blkid * BLK * PSTR4 + g * (D / 4);

    const int lastLocal = (slot_map[b] >= 0) ? (ctx - 1 - start) : -1000000;
    const float4* knp = (const float4*)knew + (size_t)(b * G + g) * (D / 4);
    const float4* vnp = (const float4*)vnew + (size_t)(b * G + g) * (D / 4);

    const uint32_t kb_a[2] = { (uint32_t)__cvta_generic_to_shared(kb[0]),
                               (uint32_t)__cvta_generic_to_shared(kb[1]) };
    const uint32_t vb_a[2] = { (uint32_t)__cvta_generic_to_shared(vb[0]),
                               (uint32_t)__cvta_generic_to_shared(vb[1]) };

    const int ntiles = (npos + TS - 1) / TS;

    // prologue: KV tile 0 -> buffers 0 (group 0). 2048 cp16 / 128 thr = 16 each.
    {
        const int rows = min(TS, npos);
        #pragma unroll
        for (int j = 0; j < 8; ++j) {
            int idx = tid + 128 * j;
            int row = idx >> 5, cc = idx & 31;
            if (row < rows) {
                uint32_t off = (uint32_t)((row * 32 + (cc ^ row)) * 16);
                const float4* src = kbase + (size_t)row * PSTR4 + cc;
                cp16(kb_a[0] + off, src);
                cp16(vb_a[0] + off, (const float4*)vbase + (size_t)row * PSTR4 + cc);
            }
        }
        cp_commit();
    }

    // q into smem, pre-scaled, layout [chunk][head]
    {
        const float4* qb = (const float4*)q + (size_t)(b * NHEADS + g * RQ) * (D / 4);
        int cc = tid >> 2, h = tid & 3;
        float4 t4 = qb[h * 32 + cc];
        t4.x *= QK_SCALE; t4.y *= QK_SCALE; t4.z *= QK_SCALE; t4.w *= QK_SCALE;
        qsm[cc * 4 + h] = t4;
    }

    float4 acc0 = make_float4(0.f, 0.f, 0.f, 0.f);
    float4 acc1 = acc0, acc2 = acc0, acc3 = acc0;
    float m_run = NEG_INF, l_run = 0.f;   // per-warp (= per-head) running state

    for (int t = 0; t < ntiles; ++t) {
        const int t0 = t * TS;
        const int cur = t & 1;

        __syncthreads();   // (A) all warps done with tile t-1 (PV reads, pt)

        // prefetch KV(t+1) into the other buffers
        if (t + 1 < ntiles) {
            const int t1 = t0 + TS;
            const int rows = min(TS, npos - t1);
            #pragma unroll
            for (int j = 0; j < 8; ++j) {
                int idx = tid + 128 * j;
                int row = idx >> 5, cc = idx & 31;
                if (row < rows) {
                    uint32_t off = (uint32_t)((row * 32 + (cc ^ row)) * 16);
                    cp16(kb_a[cur ^ 1] + off, kbase + (size_t)(t1 + row) * PSTR4 + cc);
                    cp16(vb_a[cur ^ 1] + off, vbase + (size_t)(t1 + row) * PSTR4 + cc);
                }
            }
        }
        cp_commit();        // unconditional: wait<1> == "KV(t) done"
        cp_wait<1>();
        __syncthreads();    // (B) KV(t) visible CTA-wide

        // fresh-token substitution (rare; once per CTA at most)
        const int fr = lastLocal - t0;
        if (fr >= 0 && fr < TS) {
            if (tid < 32) {
                kb[cur][fr * 32 + (tid ^ fr)] = knp[tid];
                vb[cur][fr * 32 + (tid ^ fr)] = vnp[tid];
            }
            __syncthreads();
        }

        // ---- score: warp = head, lane = position ----
        const int pvn = min(TS, npos - t0);
        float s = NEG_INF;
        {
            const float4* krow = kb[cur] + lane * 32;
            float a = 0.f;
            #pragma unroll 8
            for (int cc = 0; cc < 32; ++cc) {
                float4 k4 = krow[cc ^ lane];          // conflict-free
                float4 q4 = qsm[cc * 4 + warp];       // warp-uniform broadcast
                a += k4.x * q4.x + k4.y * q4.y + k4.z * q4.z + k4.w * q4.w;
            }
            if (lane < pvn) s = a;
        }

        // warp-local tile max (all lanes get it)
        float mt = s;
        #pragma unroll
        for (int off = 16; off > 0; off >>= 1)
            mt = fmaxf(mt, __shfl_xor_sync(0xffffffffu, mt, off));

        const float mn = fmaxf(m_run, mt);
        const float al = __expf(m_run - mn);
        m_run = mn;

        const float e = __expf(s - mn);               // 0 for invalid lanes
        ((float*)pt)[lane * 4 + warp] = e;

        float lt = e;
        #pragma unroll
        for (int off = 16; off > 0; off >>= 1)
            lt += __shfl_xor_sync(0xffffffffu, lt, off);
        l_run = l_run * al + lt;

        if (lane == 0) red[warp] = al;
        __syncthreads();    // (C) pt + al visible

        // ---- PV: warp w owns positions w, w+4, ... ----
        {
            const float al0 = red[0], al1 = red[1], al2 = red[2], al3 = red[3];
            acc0.x *= al0; acc0.y *= al0; acc0.z *= al0; acc0.w *= al0;
            acc1.x *= al1; acc1.y *= al1; acc1.z *= al1; acc1.w *= al1;
            acc2.x *= al2; acc2.y *= al2; acc2.z *= al2; acc2.w *= al2;
            acc3.x *= al3; acc3.y *= al3; acc3.z *= al3; acc3.w *= al3;

            #pragma unroll 8
            for (int p = warp; p < pvn; p += 4) {
                float4 v4 = vb[cur][p * 32 + (lane ^ p)];   // conflict-free
                float4 p4 = pt[p];                          // broadcast
                acc0.x += p4.x * v4.x; acc0.y += p4.x * v4.y;
                acc0.z += p4.x * v4.z; acc0.w += p4.x * v4.w;
                acc1.x += p4.y * v4.x; acc1.y += p4.y * v4.y;
                acc1.z += p4.y * v4.z; acc1.w += p4.y * v4.w;
                acc2.x += p4.z * v4.x; acc2.y += p4.z * v4.y;
                acc2.z += p4.z * v4.z; acc2.w += p4.z * v4.w;
                acc3.x += p4.w * v4.x; acc3.y += p4.w * v4.y;
                acc3.z += p4.w * v4.z; acc3.w += p4.w * v4.w;
            }
        }
    }

    // ---- epilogue ----
    const size_t pidx = ((size_t)(b * G + g) * MAXB + c) * RQ;
    if (lane == 0) {                     // warp w owns head w's m/l
        g_pm[pidx + warp] = m_run;
        g_pl[pidx + warp] = l_run;
    }

    __syncthreads();
    float4* ab = sm4;   // reuse K buf 0+1: [warp][head][lane] float4 = 512 f4
    ab[(warp * 4 + 0) * 32 + lane] = acc0;
    ab[(warp * 4 + 1) * 32 + lane] = acc1;
    ab[(warp * 4 + 2) * 32 + lane] = acc2;
    ab[(warp * 4 + 3) * 32 + lane] = acc3;
    __syncthreads();

    const float* abf = (const float*)ab;
    #pragma unroll
    for (int e = tid; e < RQ * D; e += 128) {
        int h = e >> 7, d = e & 127;
        float A = abf[(0 * 4 + h) * 128 + d] + abf[(1 * 4 + h) * 128 + d]
                + abf[(2 * 4 + h) * 128 + d] + abf[(3 * 4 + h) * 128 + d];
        g_pacc[(pidx + h) * D + d] = A;
    }
}

__global__ __launch_bounds__(128)
void attn_combine_kernel(const int* __restrict__ ctx_lens,
                         float* __restrict__ out)
{
    const int h = blockIdx.x;   // 0..31
    const int b = blockIdx.y;   // 0..15
    const int g  = h >> 2;
    const int hh = h & 3;
    const int nc = (ctx_lens[b] + BLK - 1) / BLK;
    const int d  = threadIdx.x;

    const size_t base = ((size_t)(b * G + g) * MAXB) * RQ + hh;

    // all 48 loads issued together (independent, predicated) -> one DRAM round
    float mv[MAXB], lv[MAXB], av[MAXB];
    #pragma unroll
    for (int c = 0; c < MAXB; ++c) {
        if (c < nc) {
            mv[c] = g_pm[base + (size_t)c * RQ];
            lv[c] = g_pl[base + (size_t)c * RQ];
            av[c] = g_pacc[(base + (size_t)c * RQ) * D + d];
        } else { mv[c] = NEG_INF; lv[c] = 0.f; av[c] = 0.f; }
    }
    float M = mv[0];
    #pragma unroll
    for (int c = 1; c < MAXB; ++c) M = fmaxf(M, mv[c]);
    float L = 0.f, A = 0.f;
    #pragma unroll
    for (int c = 0; c < MAXB; ++c) {
        const float e = __expf(mv[c] - M);
        L += e * lv[c];
        A += e * av[c];
    }
    out[((size_t)b * NHEADS + h) * D + d] = A / L;
}

extern "C" void kernel_launch(void* const* d_in, const int* in_sizes, int n_in,
                              void* d_out, int out_size)
{
    const float* q    = (const float*)d_in[0];
    const float* k    = (const float*)d_in[1];
    const float* v    = (const float*)d_in[2];
    const float* kc   = (const float*)d_in[3];
    const float* vc   = (const float*)d_in[4];
    const int*   ctx  = (const int*)d_in[5];
    const int*   btab = (const int*)d_in[6];
    const int*   smap = (const int*)d_in[7];
    float* out = (float*)d_out;

    static int smem_set = 0;
    if (!smem_set) {
        cudaFuncSetAttribute(attn_chunk_kernel,
                             cudaFuncAttributeMaxDynamicSharedMemorySize, SMEM_BYTES);
        smem_set = 1;
    }

    dim3 grid(MAXB, G, BATCH);
    attn_chunk_kernel<<<grid, 128, SMEM_BYTES>>>(q, k, v, kc, vc, ctx, btab, smap);
    attn_combine_kernel<<<dim3(NHEADS, BATCH), D>>>(ctx, out);
}